// round 1
// baseline (speedup 1.0000x reference)
#include <cuda_runtime.h>
#include <cstdint>
#include <cstdio>

// Problem constants
#define B_DIM   8192
#define IN_DIM  2048
#define H_DIM   2048
#define OUT_DIM 512
#define DEGP1   5
#define K1 (IN_DIM * DEGP1)   // 10240
#define K2 (H_DIM * DEGP1)    // 10240
#define BN_EPS 1e-5f

// -------------------- scratch (device globals; no allocs) --------------------
__device__ float g_Aexp[(size_t)B_DIM * K1];      // expanded activations (reused for layer 2)
__device__ float g_W1f [(size_t)H_DIM * K1];      // fused W1: [H][K1] row-major (B-operand, N-major)
__device__ float g_W2f [(size_t)OUT_DIM * K2];    // fused W2: [OUT][K2]
__device__ float g_H1  [(size_t)B_DIM * H_DIM];   // layer-1 pre-BN output
__device__ float g_bias1[H_DIM];
__device__ float g_bias2[OUT_DIM];
__device__ float g_partS [32 * H_DIM];
__device__ float g_partS2[32 * H_DIM];
__device__ float g_bnScale[H_DIM];
__device__ float g_bnShift[H_DIM];

// -------------------- helpers --------------------
__device__ __forceinline__ float f2tf32f(float x) {
    uint32_t r;
    asm("cvt.rna.tf32.f32 %0, %1;" : "=r"(r) : "f"(x));
    return __uint_as_float(r);
}

// -------------------- weight fusion --------------------
// W1f[h, k]: block d=0 -> w1_base[h,i]; blocks d=1..4 -> s1[h]*c1[i,h,d].  All tf32-rounded.
__global__ void fuse_w1_kernel(const float* __restrict__ w1,
                               const float* __restrict__ c1,
                               const float* __restrict__ s1) {
    long idx = (long)blockIdx.x * blockDim.x + threadIdx.x;
    if (idx >= (long)H_DIM * IN_DIM) return;
    int h = (int)(idx / IN_DIM);
    int i = (int)(idx % IN_DIM);
    float s = s1[h];
    float* dst = g_W1f + (size_t)h * K1;
    dst[i] = f2tf32f(w1[(size_t)h * IN_DIM + i]);
    const float* cp = c1 + ((size_t)i * H_DIM + h) * DEGP1;
#pragma unroll
    for (int d = 1; d < DEGP1; ++d)
        dst[(size_t)d * IN_DIM + i] = f2tf32f(s * cp[d]);
}

__global__ void fuse_w2_kernel(const float* __restrict__ w2,
                               const float* __restrict__ c2,
                               const float* __restrict__ s2) {
    long idx = (long)blockIdx.x * blockDim.x + threadIdx.x;
    if (idx >= (long)OUT_DIM * H_DIM) return;
    int o  = (int)(idx / H_DIM);
    int hh = (int)(idx % H_DIM);
    float s = s2[o];
    float* dst = g_W2f + (size_t)o * K2;
    dst[hh] = f2tf32f(w2[(size_t)o * H_DIM + hh]);
    const float* cp = c2 + ((size_t)hh * OUT_DIM + o) * DEGP1;
#pragma unroll
    for (int d = 1; d < DEGP1; ++d)
        dst[(size_t)d * H_DIM + hh] = f2tf32f(s * cp[d]);
}

// bias1[h] = b1[h] + s1[h] * sum_i c1[i,h,0]     (T0 == 1 folded into bias)
__global__ void bias1_kernel(const float* __restrict__ b1,
                             const float* __restrict__ c1,
                             const float* __restrict__ s1) {
    int h = blockIdx.x * blockDim.x + threadIdx.x;
    if (h >= H_DIM) return;
    float sum = 0.f;
    for (int i = 0; i < IN_DIM; ++i)
        sum += c1[((size_t)i * H_DIM + h) * DEGP1];
    g_bias1[h] = b1[h] + s1[h] * sum;
}

__global__ void bias2_kernel(const float* __restrict__ b2,
                             const float* __restrict__ c2,
                             const float* __restrict__ s2) {
    int o = blockIdx.x * blockDim.x + threadIdx.x;
    if (o >= OUT_DIM) return;
    float sum = 0.f;
    for (int hh = 0; hh < H_DIM; ++hh)
        sum += c2[((size_t)hh * OUT_DIM + o) * DEGP1];
    g_bias2[o] = b2[o] + s2[o] * sum;
}

// -------------------- Chebyshev expansion --------------------
// Writes [x | tanh(x) | T2 | T3 | T4] (tf32-rounded) into g_Aexp, row-major [B, 5*cols].
__global__ void expand_x_kernel(const float* __restrict__ X) {
    long idx = (long)blockIdx.x * blockDim.x + threadIdx.x;
    if (idx >= (long)B_DIM * IN_DIM) return;
    int r = (int)(idx / IN_DIM);
    int c = (int)(idx % IN_DIM);
    float x = X[idx];
    float t  = tanhf(x);
    float T2 = 2.f * t * t - 1.f;
    float T3 = 2.f * t * T2 - t;
    float T4 = 2.f * t * T3 - T2;
    float* dst = g_Aexp + (size_t)r * K1;
    dst[c]              = f2tf32f(x);
    dst[IN_DIM + c]     = f2tf32f(t);
    dst[2 * IN_DIM + c] = f2tf32f(T2);
    dst[3 * IN_DIM + c] = f2tf32f(T3);
    dst[4 * IN_DIM + c] = f2tf32f(T4);
}

// BN-fused expansion of layer-1 output.
__global__ void expand_h_kernel() {
    long idx = (long)blockIdx.x * blockDim.x + threadIdx.x;
    if (idx >= (long)B_DIM * H_DIM) return;
    int r = (int)(idx / H_DIM);
    int c = (int)(idx % H_DIM);
    float y = g_bnScale[c] * g_H1[idx] + g_bnShift[c];
    float t  = tanhf(y);
    float T2 = 2.f * t * t - 1.f;
    float T3 = 2.f * t * T2 - t;
    float T4 = 2.f * t * T3 - T2;
    float* dst = g_Aexp + (size_t)r * K2;
    dst[c]             = f2tf32f(y);
    dst[H_DIM + c]     = f2tf32f(t);
    dst[2 * H_DIM + c] = f2tf32f(T2);
    dst[3 * H_DIM + c] = f2tf32f(T3);
    dst[4 * H_DIM + c] = f2tf32f(T4);
}

// -------------------- BatchNorm statistics (deterministic 2-stage) --------------------
__global__ void bn_part_kernel() {   // grid (H/256, 32), block 256
    int col = blockIdx.x * 256 + threadIdx.x;
    int r0  = blockIdx.y * 256;
    float s = 0.f, s2 = 0.f;
    for (int r = 0; r < 256; ++r) {
        float v = g_H1[(size_t)(r0 + r) * H_DIM + col];
        s  += v;
        s2 += v * v;
    }
    g_partS [blockIdx.y * H_DIM + col] = s;
    g_partS2[blockIdx.y * H_DIM + col] = s2;
}

__global__ void bn_fin_kernel(const float* __restrict__ gamma,
                              const float* __restrict__ beta) {
    int col = blockIdx.x * blockDim.x + threadIdx.x;
    if (col >= H_DIM) return;
    float s = 0.f, s2 = 0.f;
    for (int p = 0; p < 32; ++p) {
        s  += g_partS [p * H_DIM + col];
        s2 += g_partS2[p * H_DIM + col];
    }
    float invB = 1.f / (float)B_DIM;
    float mu  = s * invB;
    float var = s2 * invB - mu * mu;
    float inv = rsqrtf(var + BN_EPS);
    float sc  = gamma[col] * inv;
    g_bnScale[col] = sc;
    g_bnShift[col] = beta[col] - mu * sc;
}

// -------------------- tf32 tensor-core GEMM: C = A[M,K] * B[N,K]^T + bias --------------------
#define GBM 128
#define GBN 128
#define GBK 32
#define GSTAGES 3
#define LDA_S 36                    // GBK + 4 pad -> conflict-free fragment LDS
#define GEMM_SMEM (GSTAGES * (GBM + GBN) * LDA_S * 4)

__global__ void __launch_bounds__(256, 1)
gemm_tf32_kernel(const float* __restrict__ A, const float* __restrict__ B,
                 const float* __restrict__ bias, float* __restrict__ C,
                 int M, int N, int K) {
    extern __shared__ float smem[];
    float* As = smem;                               // [GSTAGES][GBM][LDA_S]
    float* Bs = smem + GSTAGES * GBM * LDA_S;       // [GSTAGES][GBN][LDA_S]

    const int tid  = threadIdx.x;
    const int lane = tid & 31;
    const int warp = tid >> 5;
    const int wm = warp >> 2;     // 0..1  (64-row warp tiles)
    const int wn = warp & 3;      // 0..3  (32-col warp tiles)

    const int bM = blockIdx.y * GBM;
    const int bN = blockIdx.x * GBN;

    const float* Ag = A + (size_t)bM * K;
    const float* Bg = B + (size_t)bN * K;

    const int ldr = tid >> 3;           // 0..31 (row)
    const int ldc = (tid & 7) * 4;      // float4 column

    uint32_t asBase = (uint32_t)__cvta_generic_to_shared(As);
    uint32_t bsBase = (uint32_t)__cvta_generic_to_shared(Bs);

    auto loadTile = [&](int stage, int kt) {
        const float* ga = Ag + (size_t)ldr * K + kt * GBK + ldc;
        const float* gb = Bg + (size_t)ldr * K + kt * GBK + ldc;
        uint32_t sa = asBase + (uint32_t)(((stage * GBM + ldr) * LDA_S + ldc) * 4);
        uint32_t sb = bsBase + (uint32_t)(((stage * GBN + ldr) * LDA_S + ldc) * 4);
#pragma unroll
        for (int i = 0; i < 4; ++i) {
            asm volatile("cp.async.cg.shared.global [%0], [%1], 16;\n"
                         :: "r"(sa + i * 32 * LDA_S * 4), "l"(ga + (size_t)i * 32 * K));
            asm volatile("cp.async.cg.shared.global [%0], [%1], 16;\n"
                         :: "r"(sb + i * 32 * LDA_S * 4), "l"(gb + (size_t)i * 32 * K));
        }
    };

    float acc[4][4][4];
#pragma unroll
    for (int mi = 0; mi < 4; ++mi)
#pragma unroll
        for (int ni = 0; ni < 4; ++ni)
#pragma unroll
            for (int r = 0; r < 4; ++r) acc[mi][ni][r] = 0.f;

    const int KT = K / GBK;
#pragma unroll
    for (int s = 0; s < GSTAGES - 1; ++s) {
        loadTile(s, s);
        asm volatile("cp.async.commit_group;\n");
    }

    const int aRow = wm * 64 + (lane >> 2);
    const int bRow = wn * 32 + (lane >> 2);
    const int kCol = lane & 3;

    for (int kt = 0; kt < KT; ++kt) {
        asm volatile("cp.async.wait_group %0;\n" :: "n"(GSTAGES - 2));
        __syncthreads();
        int s = kt % GSTAGES;
        int nkt = kt + GSTAGES - 1;
        if (nkt < KT) loadTile(nkt % GSTAGES, nkt);
        asm volatile("cp.async.commit_group;\n");

        const float* as = As + s * GBM * LDA_S;
        const float* bs = Bs + s * GBN * LDA_S;
#pragma unroll
        for (int kk = 0; kk < GBK / 8; ++kk) {
            uint32_t af[4][4], bf[4][2];
            int c0 = kk * 8 + kCol;
#pragma unroll
            for (int mi = 0; mi < 4; ++mi) {
                const float* p = as + (aRow + mi * 16) * LDA_S;
                af[mi][0] = __float_as_uint(p[c0]);               // (row,   c0)
                af[mi][1] = __float_as_uint(p[8 * LDA_S + c0]);   // (row+8, c0)
                af[mi][2] = __float_as_uint(p[c0 + 4]);           // (row,   c0+4)
                af[mi][3] = __float_as_uint(p[8 * LDA_S + c0 + 4]); // (row+8, c0+4)
            }
#pragma unroll
            for (int ni = 0; ni < 4; ++ni) {
                const float* p = bs + (bRow + ni * 8) * LDA_S;
                bf[ni][0] = __float_as_uint(p[c0]);
                bf[ni][1] = __float_as_uint(p[c0 + 4]);
            }
#pragma unroll
            for (int mi = 0; mi < 4; ++mi)
#pragma unroll
                for (int ni = 0; ni < 4; ++ni) {
                    asm volatile(
                        "mma.sync.aligned.m16n8k8.row.col.f32.tf32.tf32.f32 "
                        "{%0,%1,%2,%3}, {%4,%5,%6,%7}, {%8,%9}, {%0,%1,%2,%3};\n"
                        : "+f"(acc[mi][ni][0]), "+f"(acc[mi][ni][1]),
                          "+f"(acc[mi][ni][2]), "+f"(acc[mi][ni][3])
                        : "r"(af[mi][0]), "r"(af[mi][1]), "r"(af[mi][2]), "r"(af[mi][3]),
                          "r"(bf[ni][0]), "r"(bf[ni][1]));
                }
        }
    }

    // epilogue: C += bias
#pragma unroll
    for (int mi = 0; mi < 4; ++mi) {
        int r0 = bM + wm * 64 + mi * 16 + (lane >> 2);
#pragma unroll
        for (int ni = 0; ni < 4; ++ni) {
            int c = bN + wn * 32 + ni * 8 + (lane & 3) * 2;
            float b0 = bias[c], b1v = bias[c + 1];
            float2 v0 = make_float2(acc[mi][ni][0] + b0, acc[mi][ni][1] + b1v);
            float2 v1 = make_float2(acc[mi][ni][2] + b0, acc[mi][ni][3] + b1v);
            *reinterpret_cast<float2*>(&C[(size_t)r0 * N + c])       = v0;
            *reinterpret_cast<float2*>(&C[(size_t)(r0 + 8) * N + c]) = v1;
        }
    }
}

// -------------------- launch --------------------
extern "C" void kernel_launch(void* const* d_in, const int* in_sizes, int n_in,
                              void* d_out, int out_size) {
    const float* x     = (const float*)d_in[0];
    const float* w1    = (const float*)d_in[1];
    const float* b1    = (const float*)d_in[2];
    const float* c1    = (const float*)d_in[3];
    const float* s1    = (const float*)d_in[4];
    const float* gamma = (const float*)d_in[5];
    const float* beta  = (const float*)d_in[6];
    const float* w2    = (const float*)d_in[7];
    const float* b2    = (const float*)d_in[8];
    const float* c2    = (const float*)d_in[9];
    const float* s2    = (const float*)d_in[10];
    float* out = (float*)d_out;

    cudaFuncSetAttribute(gemm_tf32_kernel,
                         cudaFuncAttributeMaxDynamicSharedMemorySize, GEMM_SMEM);

    void *pA, *pW1, *pW2, *pH1, *pB1, *pB2;
    cudaGetSymbolAddress(&pA,  g_Aexp);
    cudaGetSymbolAddress(&pW1, g_W1f);
    cudaGetSymbolAddress(&pW2, g_W2f);
    cudaGetSymbolAddress(&pH1, g_H1);
    cudaGetSymbolAddress(&pB1, g_bias1);
    cudaGetSymbolAddress(&pB2, g_bias2);

    // weight fusion + biases
    fuse_w1_kernel<<<(H_DIM * IN_DIM + 255) / 256, 256>>>(w1, c1, s1);
    fuse_w2_kernel<<<(OUT_DIM * H_DIM + 255) / 256, 256>>>(w2, c2, s2);
    bias1_kernel<<<H_DIM / 256, 256>>>(b1, c1, s1);
    bias2_kernel<<<OUT_DIM / 256, 256>>>(b2, c2, s2);

    // layer 1
    expand_x_kernel<<<(B_DIM * IN_DIM) / 256, 256>>>(x);
    {
        dim3 grid(H_DIM / GBN, B_DIM / GBM);   // (16, 64)
        gemm_tf32_kernel<<<grid, 256, GEMM_SMEM>>>(
            (const float*)pA, (const float*)pW1, (const float*)pB1,
            (float*)pH1, B_DIM, H_DIM, K1);
    }

    // batchnorm stats
    bn_part_kernel<<<dim3(H_DIM / 256, 32), 256>>>();
    bn_fin_kernel<<<H_DIM / 256, 256>>>(gamma, beta);

    // layer 2
    expand_h_kernel<<<(B_DIM * H_DIM) / 256, 256>>>();
    {
        dim3 grid(OUT_DIM / GBN, B_DIM / GBM); // (4, 64)
        gemm_tf32_kernel<<<grid, 256, GEMM_SMEM>>>(
            (const float*)pA, (const float*)pW2, (const float*)pB2,
            out, B_DIM, OUT_DIM, K2);
    }
}

// round 3
// speedup vs baseline: 1.0872x; 1.0872x over previous
#include <cuda_runtime.h>
#include <cstdint>
#include <cstdio>

// ------------------------------------------------------------------
// Problem constants
// ------------------------------------------------------------------
#define B_DIM   8192
#define IN_DIM  2048
#define H_DIM   2048
#define OUT_DIM 512
#define DEGP1   5
#define K_TOT (IN_DIM * DEGP1)   // 10240
#define BN_EPS 1e-5f

// ------------------------------------------------------------------
// Scratch (device globals; no runtime allocation)
// ------------------------------------------------------------------
__device__ float g_Aexp[(size_t)B_DIM * K_TOT];    // expanded activations
__device__ float g_W1f [(size_t)H_DIM * K_TOT];    // fused W1 [H][K]
__device__ float g_W2f [(size_t)OUT_DIM * K_TOT];  // fused W2 [OUT][K]
__device__ float g_H1  [(size_t)B_DIM * H_DIM];    // layer-1 pre-BN output
__device__ float g_c1d0[(size_t)H_DIM * IN_DIM];   // s1[h]*c1[i,h,0] staged coalesced
__device__ float g_c2d0[(size_t)OUT_DIM * H_DIM];
__device__ float g_bias1[H_DIM];
__device__ float g_bias2[OUT_DIM];
__device__ float g_partS [32 * H_DIM];
__device__ float g_partS2[32 * H_DIM];
__device__ float g_bnScale[H_DIM];
__device__ float g_bnShift[H_DIM];

// ------------------------------------------------------------------
// helpers
// ------------------------------------------------------------------
__device__ __forceinline__ float f2tf32f(float x) {
    uint32_t r;
    asm("cvt.rna.tf32.f32 %0, %1;" : "=r"(r) : "f"(x));
    return __uint_as_float(r);
}

// ------------------------------------------------------------------
// Weight fusion (+ staged d=0 slice for fast bias reduction)
// ------------------------------------------------------------------
__global__ void fuse_w1_kernel(const float* __restrict__ w1,
                               const float* __restrict__ c1,
                               const float* __restrict__ s1) {
    long idx = (long)blockIdx.x * blockDim.x + threadIdx.x;
    if (idx >= (long)H_DIM * IN_DIM) return;
    int h = (int)(idx / IN_DIM);
    int i = (int)(idx % IN_DIM);
    float s = s1[h];
    float* dst = g_W1f + (size_t)h * K_TOT;
    dst[i] = f2tf32f(w1[(size_t)h * IN_DIM + i]);
    const float* cp = c1 + ((size_t)i * H_DIM + h) * DEGP1;
    g_c1d0[idx] = s * cp[0];
#pragma unroll
    for (int d = 1; d < DEGP1; ++d)
        dst[(size_t)d * IN_DIM + i] = f2tf32f(s * cp[d]);
}

__global__ void fuse_w2_kernel(const float* __restrict__ w2,
                               const float* __restrict__ c2,
                               const float* __restrict__ s2) {
    long idx = (long)blockIdx.x * blockDim.x + threadIdx.x;
    if (idx >= (long)OUT_DIM * H_DIM) return;
    int o  = (int)(idx / H_DIM);
    int hh = (int)(idx % H_DIM);
    float s = s2[o];
    float* dst = g_W2f + (size_t)o * K_TOT;
    dst[hh] = f2tf32f(w2[(size_t)o * H_DIM + hh]);
    const float* cp = c2 + ((size_t)hh * OUT_DIM + o) * DEGP1;
    g_c2d0[idx] = s * cp[0];
#pragma unroll
    for (int d = 1; d < DEGP1; ++d)
        dst[(size_t)d * H_DIM + hh] = f2tf32f(s * cp[d]);
}

// bias[o] = b[o] + sum_j staged[o*len + j]   (contiguous, one block per o)
__global__ void bias_reduce_kernel(const float* __restrict__ staged,
                                   const float* __restrict__ b,
                                   float* __restrict__ dst, int len) {
    __shared__ float red[256];
    int o = blockIdx.x;
    const float* src = staged + (size_t)o * len;
    float s = 0.f;
    for (int j = threadIdx.x; j < len; j += 256) s += src[j];
    red[threadIdx.x] = s;
    __syncthreads();
    for (int st = 128; st > 0; st >>= 1) {
        if (threadIdx.x < st) red[threadIdx.x] += red[threadIdx.x + st];
        __syncthreads();
    }
    if (threadIdx.x == 0) dst[o] = b[o] + red[0];
}

// ------------------------------------------------------------------
// Chebyshev expansion
// ------------------------------------------------------------------
__global__ void expand_x_kernel(const float* __restrict__ X) {
    long idx = (long)blockIdx.x * blockDim.x + threadIdx.x;
    if (idx >= (long)B_DIM * IN_DIM) return;
    int r = (int)(idx / IN_DIM);
    int c = (int)(idx % IN_DIM);
    float x = X[idx];
    float t  = tanhf(x);
    float T2 = 2.f * t * t - 1.f;
    float T3 = 2.f * t * T2 - t;
    float T4 = 2.f * t * T3 - T2;
    float* dst = g_Aexp + (size_t)r * K_TOT;
    dst[c]              = f2tf32f(x);
    dst[IN_DIM + c]     = f2tf32f(t);
    dst[2 * IN_DIM + c] = f2tf32f(T2);
    dst[3 * IN_DIM + c] = f2tf32f(T3);
    dst[4 * IN_DIM + c] = f2tf32f(T4);
}

__global__ void expand_h_kernel() {
    long idx = (long)blockIdx.x * blockDim.x + threadIdx.x;
    if (idx >= (long)B_DIM * H_DIM) return;
    int r = (int)(idx / H_DIM);
    int c = (int)(idx % H_DIM);
    float y = g_bnScale[c] * g_H1[idx] + g_bnShift[c];
    float t  = tanhf(y);
    float T2 = 2.f * t * t - 1.f;
    float T3 = 2.f * t * T2 - t;
    float T4 = 2.f * t * T3 - T2;
    float* dst = g_Aexp + (size_t)r * K_TOT;
    dst[c]             = f2tf32f(y);
    dst[H_DIM + c]     = f2tf32f(t);
    dst[2 * H_DIM + c] = f2tf32f(T2);
    dst[3 * H_DIM + c] = f2tf32f(T3);
    dst[4 * H_DIM + c] = f2tf32f(T4);
}

// ------------------------------------------------------------------
// BatchNorm statistics (deterministic 2-stage)
// ------------------------------------------------------------------
__global__ void bn_part_kernel() {   // grid (H/256, 32), block 256
    int col = blockIdx.x * 256 + threadIdx.x;
    int r0  = blockIdx.y * 256;
    float s = 0.f, s2 = 0.f;
    for (int r = 0; r < 256; ++r) {
        float v = g_H1[(size_t)(r0 + r) * H_DIM + col];
        s  += v;
        s2 += v * v;
    }
    g_partS [blockIdx.y * H_DIM + col] = s;
    g_partS2[blockIdx.y * H_DIM + col] = s2;
}

__global__ void bn_fin_kernel(const float* __restrict__ gamma,
                              const float* __restrict__ beta) {
    int col = blockIdx.x * blockDim.x + threadIdx.x;
    if (col >= H_DIM) return;
    float s = 0.f, s2 = 0.f;
    for (int p = 0; p < 32; ++p) {
        s  += g_partS [p * H_DIM + col];
        s2 += g_partS2[p * H_DIM + col];
    }
    float invB = 1.f / (float)B_DIM;
    float mu  = s * invB;
    float var = s2 * invB - mu * mu;
    float inv = rsqrtf(var + BN_EPS);
    float sc  = gamma[col] * inv;
    g_bnScale[col] = sc;
    g_bnShift[col] = beta[col] - mu * sc;
}

// ------------------------------------------------------------------
// tf32 tensor-core GEMM: C = A[M,K] * B[N,K]^T + bias
// 128x256 block tile, 64x64 warp tile, 8 warps, 3-stage cp.async pipeline
// ------------------------------------------------------------------
#define GBM 128
#define GBN 256
#define GBK 32
#define GSTAGES 3
#define LDP 36                                    // GBK + 4 pad
#define A_STG (GBM * LDP)                         // floats per A stage
#define B_STG (GBN * LDP)
#define GEMM_SMEM (GSTAGES * (A_STG + B_STG) * 4) // 165888 B

__global__ void __launch_bounds__(256, 1)
gemm_tf32_kernel(const float* __restrict__ A, const float* __restrict__ B,
                 const float* __restrict__ bias, float* __restrict__ C,
                 int M, int N, int K) {
    extern __shared__ float smem[];
    float* As = smem;                        // [GSTAGES][GBM][LDP]
    float* Bs = smem + GSTAGES * A_STG;      // [GSTAGES][GBN][LDP]

    const int tid  = threadIdx.x;
    const int lane = tid & 31;
    const int warp = tid >> 5;
    const int wm = warp >> 2;     // 0..1  -> 64-row warp tile
    const int wn = warp & 3;      // 0..3  -> 64-col warp tile

    const int bM = blockIdx.y * GBM;
    const int bN = blockIdx.x * GBN;

    const float* Ag = A + (size_t)bM * K;
    const float* Bg = B + (size_t)bN * K;

    const int ldr = tid >> 3;           // 0..31 (row within 32-row group)
    const int ldc = (tid & 7) * 4;      // float4 column

    uint32_t asBase = (uint32_t)__cvta_generic_to_shared(As);
    uint32_t bsBase = (uint32_t)__cvta_generic_to_shared(Bs);

    auto loadTile = [&](int stage, int kt) {
        const float* ga = Ag + (size_t)ldr * K + kt * GBK + ldc;
        const float* gb = Bg + (size_t)ldr * K + kt * GBK + ldc;
        uint32_t sa = asBase + (uint32_t)(((stage * GBM + ldr) * LDP + ldc) * 4);
        uint32_t sbp = bsBase + (uint32_t)(((stage * GBN + ldr) * LDP + ldc) * 4);
#pragma unroll
        for (int i = 0; i < 4; ++i)
            asm volatile("cp.async.cg.shared.global [%0], [%1], 16;\n"
                         :: "r"(sa + i * 32 * LDP * 4), "l"(ga + (size_t)i * 32 * K));
#pragma unroll
        for (int i = 0; i < 8; ++i)
            asm volatile("cp.async.cg.shared.global [%0], [%1], 16;\n"
                         :: "r"(sbp + i * 32 * LDP * 4), "l"(gb + (size_t)i * 32 * K));
    };

    float acc[4][8][4];
#pragma unroll
    for (int mi = 0; mi < 4; ++mi)
#pragma unroll
        for (int ni = 0; ni < 8; ++ni)
#pragma unroll
            for (int r = 0; r < 4; ++r) acc[mi][ni][r] = 0.f;

    const int KT = K / GBK;
#pragma unroll
    for (int s = 0; s < GSTAGES - 1; ++s) {
        loadTile(s, s);
        asm volatile("cp.async.commit_group;\n");
    }

    const int aRow = wm * 64 + (lane >> 2);
    const int bRow = wn * 64 + (lane >> 2);
    const int kCol = lane & 3;

    for (int kt = 0; kt < KT; ++kt) {
        asm volatile("cp.async.wait_group %0;\n" :: "n"(GSTAGES - 2));
        __syncthreads();
        int s = kt % GSTAGES;
        int nkt = kt + GSTAGES - 1;
        if (nkt < KT) loadTile(nkt % GSTAGES, nkt);
        asm volatile("cp.async.commit_group;\n");

        const float* as = As + s * A_STG;
        const float* bs = Bs + s * B_STG;
#pragma unroll
        for (int kk = 0; kk < GBK / 8; ++kk) {
            uint32_t af[4][4], bf[8][2];
            const int c0 = kk * 8 + kCol;
#pragma unroll
            for (int mi = 0; mi < 4; ++mi) {
                const float* p = as + (aRow + mi * 16) * LDP;
                af[mi][0] = __float_as_uint(p[c0]);
                af[mi][1] = __float_as_uint(p[8 * LDP + c0]);
                af[mi][2] = __float_as_uint(p[c0 + 4]);
                af[mi][3] = __float_as_uint(p[8 * LDP + c0 + 4]);
            }
#pragma unroll
            for (int ni = 0; ni < 8; ++ni) {
                const float* p = bs + (bRow + ni * 8) * LDP;
                bf[ni][0] = __float_as_uint(p[c0]);
                bf[ni][1] = __float_as_uint(p[c0 + 4]);
            }
#pragma unroll
            for (int mi = 0; mi < 4; ++mi)
#pragma unroll
                for (int ni = 0; ni < 8; ++ni) {
                    asm volatile(
                        "mma.sync.aligned.m16n8k8.row.col.f32.tf32.tf32.f32 "
                        "{%0,%1,%2,%3}, {%4,%5,%6,%7}, {%8,%9}, {%0,%1,%2,%3};\n"
                        : "+f"(acc[mi][ni][0]), "+f"(acc[mi][ni][1]),
                          "+f"(acc[mi][ni][2]), "+f"(acc[mi][ni][3])
                        : "r"(af[mi][0]), "r"(af[mi][1]), "r"(af[mi][2]), "r"(af[mi][3]),
                          "r"(bf[ni][0]), "r"(bf[ni][1]));
                }
        }
    }

    // epilogue: C = acc + bias
#pragma unroll
    for (int mi = 0; mi < 4; ++mi) {
        int r0 = bM + wm * 64 + mi * 16 + (lane >> 2);
#pragma unroll
        for (int ni = 0; ni < 8; ++ni) {
            int c = bN + wn * 64 + ni * 8 + (lane & 3) * 2;
            float b0 = bias[c], b1v = bias[c + 1];
            float2 v0 = make_float2(acc[mi][ni][0] + b0, acc[mi][ni][1] + b1v);
            float2 v1 = make_float2(acc[mi][ni][2] + b0, acc[mi][ni][3] + b1v);
            *reinterpret_cast<float2*>(&C[(size_t)r0 * N + c])       = v0;
            *reinterpret_cast<float2*>(&C[(size_t)(r0 + 8) * N + c]) = v1;
        }
    }
}

// ------------------------------------------------------------------
// launch
// ------------------------------------------------------------------
extern "C" void kernel_launch(void* const* d_in, const int* in_sizes, int n_in,
                              void* d_out, int out_size) {
    const float* x     = (const float*)d_in[0];
    const float* w1    = (const float*)d_in[1];
    const float* b1    = (const float*)d_in[2];
    const float* c1    = (const float*)d_in[3];
    const float* s1    = (const float*)d_in[4];
    const float* gamma = (const float*)d_in[5];
    const float* beta  = (const float*)d_in[6];
    const float* w2    = (const float*)d_in[7];
    const float* b2    = (const float*)d_in[8];
    const float* c2    = (const float*)d_in[9];
    const float* s2    = (const float*)d_in[10];
    float* out = (float*)d_out;

    cudaFuncSetAttribute(gemm_tf32_kernel,
                         cudaFuncAttributeMaxDynamicSharedMemorySize, GEMM_SMEM);

    void *pA, *pW1, *pW2, *pH1, *pB1, *pB2, *pC1d0, *pC2d0;
    cudaGetSymbolAddress(&pA,    g_Aexp);
    cudaGetSymbolAddress(&pW1,   g_W1f);
    cudaGetSymbolAddress(&pW2,   g_W2f);
    cudaGetSymbolAddress(&pH1,   g_H1);
    cudaGetSymbolAddress(&pB1,   g_bias1);
    cudaGetSymbolAddress(&pB2,   g_bias2);
    cudaGetSymbolAddress(&pC1d0, g_c1d0);
    cudaGetSymbolAddress(&pC2d0, g_c2d0);

    // weight fusion + bias (staged, coalesced reductions)
    fuse_w1_kernel<<<(H_DIM * IN_DIM + 255) / 256, 256>>>(w1, c1, s1);
    fuse_w2_kernel<<<(OUT_DIM * H_DIM + 255) / 256, 256>>>(w2, c2, s2);
    bias_reduce_kernel<<<H_DIM, 256>>>((const float*)pC1d0, b1, (float*)pB1, IN_DIM);
    bias_reduce_kernel<<<OUT_DIM, 256>>>((const float*)pC2d0, b2, (float*)pB2, H_DIM);

    // layer 1
    expand_x_kernel<<<(B_DIM * IN_DIM) / 256, 256>>>(x);
    {
        dim3 grid(H_DIM / GBN, B_DIM / GBM);   // (8, 64)
        gemm_tf32_kernel<<<grid, 256, GEMM_SMEM>>>(
            (const float*)pA, (const float*)pW1, (const float*)pB1,
            (float*)pH1, B_DIM, H_DIM, K_TOT);
    }

    // batchnorm stats
    bn_part_kernel<<<dim3(H_DIM / 256, 32), 256>>>();
    bn_fin_kernel<<<H_DIM / 256, 256>>>(gamma, beta);

    // layer 2
    expand_h_kernel<<<(B_DIM * H_DIM) / 256, 256>>>();
    {
        dim3 grid(OUT_DIM / GBN, B_DIM / GBM); // (2, 64)
        gemm_tf32_kernel<<<grid, 256, GEMM_SMEM>>>(
            (const float*)pA, (const float*)pW2, (const float*)pB2,
            out, B_DIM, OUT_DIM, K_TOT);
    }
}

// round 4
// speedup vs baseline: 1.1027x; 1.0142x over previous
#include <cuda_runtime.h>
#include <cstdint>
#include <cstdio>

// ------------------------------------------------------------------
// Problem constants
// ------------------------------------------------------------------
#define B_DIM   8192
#define IN_DIM  2048
#define H_DIM   2048
#define OUT_DIM 512
#define DEGP1   5
#define K_TOT (IN_DIM * DEGP1)   // 10240
#define BN_EPS 1e-5f

// ------------------------------------------------------------------
// Scratch (device globals; no runtime allocation)
// ------------------------------------------------------------------
__device__ float g_Aexp[(size_t)B_DIM * K_TOT];    // expanded activations
__device__ float g_W1f [(size_t)H_DIM * K_TOT];    // fused W1 [H][K]
__device__ float g_W2f [(size_t)OUT_DIM * K_TOT];  // fused W2 [OUT][K]
__device__ float g_H1  [(size_t)B_DIM * H_DIM];    // layer-1 pre-BN output
__device__ float g_c1d0[(size_t)H_DIM * IN_DIM];   // s1[h]*c1[i,h,0] staged coalesced
__device__ float g_c2d0[(size_t)OUT_DIM * H_DIM];
__device__ float g_bias1[H_DIM];
__device__ float g_bias2[OUT_DIM];
__device__ float g_partS [32 * H_DIM];
__device__ float g_partS2[32 * H_DIM];
__device__ float g_bnScale[H_DIM];
__device__ float g_bnShift[H_DIM];

// ------------------------------------------------------------------
// helpers
// ------------------------------------------------------------------
__device__ __forceinline__ float f2tf32f(float x) {
    uint32_t r;
    asm("cvt.rna.tf32.f32 %0, %1;" : "=r"(r) : "f"(x));
    return __uint_as_float(r);
}

__device__ __forceinline__ void ldsm_x4(uint32_t& r0, uint32_t& r1,
                                        uint32_t& r2, uint32_t& r3, uint32_t addr) {
    asm volatile("ldmatrix.sync.aligned.m8n8.x4.shared.b16 {%0,%1,%2,%3}, [%4];"
                 : "=r"(r0), "=r"(r1), "=r"(r2), "=r"(r3) : "r"(addr));
}

// ------------------------------------------------------------------
// Weight fusion (+ staged d=0 slice for fast bias reduction)
// ------------------------------------------------------------------
__global__ void fuse_w1_kernel(const float* __restrict__ w1,
                               const float* __restrict__ c1,
                               const float* __restrict__ s1) {
    long idx = (long)blockIdx.x * blockDim.x + threadIdx.x;
    if (idx >= (long)H_DIM * IN_DIM) return;
    int h = (int)(idx / IN_DIM);
    int i = (int)(idx % IN_DIM);
    float s = s1[h];
    float* dst = g_W1f + (size_t)h * K_TOT;
    dst[i] = f2tf32f(w1[(size_t)h * IN_DIM + i]);
    const float* cp = c1 + ((size_t)i * H_DIM + h) * DEGP1;
    g_c1d0[idx] = s * cp[0];
#pragma unroll
    for (int d = 1; d < DEGP1; ++d)
        dst[(size_t)d * IN_DIM + i] = f2tf32f(s * cp[d]);
}

__global__ void fuse_w2_kernel(const float* __restrict__ w2,
                               const float* __restrict__ c2,
                               const float* __restrict__ s2) {
    long idx = (long)blockIdx.x * blockDim.x + threadIdx.x;
    if (idx >= (long)OUT_DIM * H_DIM) return;
    int o  = (int)(idx / H_DIM);
    int hh = (int)(idx % H_DIM);
    float s = s2[o];
    float* dst = g_W2f + (size_t)o * K_TOT;
    dst[hh] = f2tf32f(w2[(size_t)o * H_DIM + hh]);
    const float* cp = c2 + ((size_t)hh * OUT_DIM + o) * DEGP1;
    g_c2d0[idx] = s * cp[0];
#pragma unroll
    for (int d = 1; d < DEGP1; ++d)
        dst[(size_t)d * H_DIM + hh] = f2tf32f(s * cp[d]);
}

// bias[o] = b[o] + sum_j staged[o*len + j]   (contiguous, one block per o)
__global__ void bias_reduce_kernel(const float* __restrict__ staged,
                                   const float* __restrict__ b,
                                   float* __restrict__ dst, int len) {
    __shared__ float red[256];
    int o = blockIdx.x;
    const float* src = staged + (size_t)o * len;
    float s = 0.f;
    for (int j = threadIdx.x; j < len; j += 256) s += src[j];
    red[threadIdx.x] = s;
    __syncthreads();
    for (int st = 128; st > 0; st >>= 1) {
        if (threadIdx.x < st) red[threadIdx.x] += red[threadIdx.x + st];
        __syncthreads();
    }
    if (threadIdx.x == 0) dst[o] = b[o] + red[0];
}

// ------------------------------------------------------------------
// Chebyshev expansion
// ------------------------------------------------------------------
__global__ void expand_x_kernel(const float* __restrict__ X) {
    long idx = (long)blockIdx.x * blockDim.x + threadIdx.x;
    if (idx >= (long)B_DIM * IN_DIM) return;
    int r = (int)(idx / IN_DIM);
    int c = (int)(idx % IN_DIM);
    float x = X[idx];
    float t  = tanhf(x);
    float T2 = 2.f * t * t - 1.f;
    float T3 = 2.f * t * T2 - t;
    float T4 = 2.f * t * T3 - T2;
    float* dst = g_Aexp + (size_t)r * K_TOT;
    dst[c]              = f2tf32f(x);
    dst[IN_DIM + c]     = f2tf32f(t);
    dst[2 * IN_DIM + c] = f2tf32f(T2);
    dst[3 * IN_DIM + c] = f2tf32f(T3);
    dst[4 * IN_DIM + c] = f2tf32f(T4);
}

__global__ void expand_h_kernel() {
    long idx = (long)blockIdx.x * blockDim.x + threadIdx.x;
    if (idx >= (long)B_DIM * H_DIM) return;
    int r = (int)(idx / H_DIM);
    int c = (int)(idx % H_DIM);
    float y = g_bnScale[c] * g_H1[idx] + g_bnShift[c];
    float t  = tanhf(y);
    float T2 = 2.f * t * t - 1.f;
    float T3 = 2.f * t * T2 - t;
    float T4 = 2.f * t * T3 - T2;
    float* dst = g_Aexp + (size_t)r * K_TOT;
    dst[c]             = f2tf32f(y);
    dst[H_DIM + c]     = f2tf32f(t);
    dst[2 * H_DIM + c] = f2tf32f(T2);
    dst[3 * H_DIM + c] = f2tf32f(T3);
    dst[4 * H_DIM + c] = f2tf32f(T4);
}

// ------------------------------------------------------------------
// BatchNorm statistics (deterministic 2-stage)
// ------------------------------------------------------------------
__global__ void bn_part_kernel() {   // grid (H/256, 32), block 256
    int col = blockIdx.x * 256 + threadIdx.x;
    int r0  = blockIdx.y * 256;
    float s = 0.f, s2 = 0.f;
    for (int r = 0; r < 256; ++r) {
        float v = g_H1[(size_t)(r0 + r) * H_DIM + col];
        s  += v;
        s2 += v * v;
    }
    g_partS [blockIdx.y * H_DIM + col] = s;
    g_partS2[blockIdx.y * H_DIM + col] = s2;
}

__global__ void bn_fin_kernel(const float* __restrict__ gamma,
                              const float* __restrict__ beta) {
    int col = blockIdx.x * blockDim.x + threadIdx.x;
    if (col >= H_DIM) return;
    float s = 0.f, s2 = 0.f;
    for (int p = 0; p < 32; ++p) {
        s  += g_partS [p * H_DIM + col];
        s2 += g_partS2[p * H_DIM + col];
    }
    float invB = 1.f / (float)B_DIM;
    float mu  = s * invB;
    float var = s2 * invB - mu * mu;
    float inv = rsqrtf(var + BN_EPS);
    float sc  = gamma[col] * inv;
    g_bnScale[col] = sc;
    g_bnShift[col] = beta[col] - mu * sc;
}

// ------------------------------------------------------------------
// tf32 tensor-core GEMM: C = A[M,K] * B[N,K]^T + bias
// 128x256 block tile, 64x64 warp tile, 8 warps, 3-stage cp.async pipeline,
// ldmatrix.x4 fragment feeding (4 scalar LDS -> 1 LDSM.x4)
// ------------------------------------------------------------------
#define GBM 128
#define GBN 256
#define GBK 32
#define GSTAGES 3
#define LDP 36                                    // GBK + 4 pad (row stride 144B: LDSM conflict-free)
#define A_STG (GBM * LDP)
#define B_STG (GBN * LDP)
#define GEMM_SMEM (GSTAGES * (A_STG + B_STG) * 4) // 165888 B

__global__ void __launch_bounds__(256, 1)
gemm_tf32_kernel(const float* __restrict__ A, const float* __restrict__ B,
                 const float* __restrict__ bias, float* __restrict__ C,
                 int M, int N, int K) {
    extern __shared__ float smem[];
    float* As = smem;                        // [GSTAGES][GBM][LDP]
    float* Bs = smem + GSTAGES * A_STG;      // [GSTAGES][GBN][LDP]

    const int tid  = threadIdx.x;
    const int lane = tid & 31;
    const int warp = tid >> 5;
    const int wm = warp >> 2;     // 0..1  -> 64-row warp tile
    const int wn = warp & 3;      // 0..3  -> 64-col warp tile

    const int bM = blockIdx.y * GBM;
    const int bN = blockIdx.x * GBN;

    const float* Ag = A + (size_t)bM * K;
    const float* Bg = B + (size_t)bN * K;

    const int ldr = tid >> 3;           // 0..31
    const int ldc = (tid & 7) * 4;      // float4 column

    uint32_t asBase = (uint32_t)__cvta_generic_to_shared(As);
    uint32_t bsBase = (uint32_t)__cvta_generic_to_shared(Bs);

    auto loadTile = [&](int stage, int kt) {
        const float* ga = Ag + (size_t)ldr * K + kt * GBK + ldc;
        const float* gb = Bg + (size_t)ldr * K + kt * GBK + ldc;
        uint32_t sa = asBase + (uint32_t)(((stage * GBM + ldr) * LDP + ldc) * 4);
        uint32_t sbp = bsBase + (uint32_t)(((stage * GBN + ldr) * LDP + ldc) * 4);
#pragma unroll
        for (int i = 0; i < 4; ++i)
            asm volatile("cp.async.cg.shared.global [%0], [%1], 16;\n"
                         :: "r"(sa + i * 32 * LDP * 4), "l"(ga + (size_t)i * 32 * K));
#pragma unroll
        for (int i = 0; i < 8; ++i)
            asm volatile("cp.async.cg.shared.global [%0], [%1], 16;\n"
                         :: "r"(sbp + i * 32 * LDP * 4), "l"(gb + (size_t)i * 32 * K));
    };

    float acc[4][8][4];
#pragma unroll
    for (int mi = 0; mi < 4; ++mi)
#pragma unroll
        for (int ni = 0; ni < 8; ++ni)
#pragma unroll
            for (int r = 0; r < 4; ++r) acc[mi][ni][r] = 0.f;

    const int KT = K / GBK;
#pragma unroll
    for (int s = 0; s < GSTAGES - 1; ++s) {
        loadTile(s, s);
        asm volatile("cp.async.commit_group;\n");
    }

    // -------- ldmatrix per-lane base addresses (stage-0, kk-0) --------
    // x4 tile id j = lane>>3, row within tile = lane&7.
    const int jj = lane >> 3;
    const int lr = lane & 7;
    // A tiles: j0={rows 0-7, words 0-3}, j1={rows 8-15, w0-3}, j2={rows 0-7, w4-7}, j3={rows 8-15, w4-7}
    uint32_t aAddr[4];
#pragma unroll
    for (int mi = 0; mi < 4; ++mi) {
        int row = wm * 64 + mi * 16 + ((jj & 1) << 3) + lr;
        aAddr[mi] = asBase + (uint32_t)((row * LDP) * 4 + ((jj >> 1) << 4));
    }
    // B tiles (pair p covers ni=2p,2p+1): j0={n 0-7, w0-3}, j1={n 0-7, w4-7}, j2={n 8-15, w0-3}, j3={n 8-15, w4-7}
    uint32_t bAddr[4];
#pragma unroll
    for (int p = 0; p < 4; ++p) {
        int row = wn * 64 + p * 16 + ((jj >> 1) << 3) + lr;
        bAddr[p] = bsBase + (uint32_t)((row * LDP) * 4 + ((jj & 1) << 4));
    }

    for (int kt = 0; kt < KT; ++kt) {
        asm volatile("cp.async.wait_group %0;\n" :: "n"(GSTAGES - 2));
        __syncthreads();
        int s = kt % GSTAGES;
        int nkt = kt + GSTAGES - 1;
        if (nkt < KT) loadTile(nkt % GSTAGES, nkt);
        asm volatile("cp.async.commit_group;\n");

        const uint32_t aStg = (uint32_t)(s * A_STG * 4);
        const uint32_t bStg = (uint32_t)(s * B_STG * 4);
#pragma unroll
        for (int kk = 0; kk < GBK / 8; ++kk) {
            const uint32_t kOff = kk * 32;   // 8 tf32 = 32 bytes
            uint32_t af[4][4], bf[8][2];
#pragma unroll
            for (int mi = 0; mi < 4; ++mi)
                ldsm_x4(af[mi][0], af[mi][1], af[mi][2], af[mi][3],
                        aAddr[mi] + aStg + kOff);
#pragma unroll
            for (int p = 0; p < 4; ++p)
                ldsm_x4(bf[2 * p][0], bf[2 * p][1], bf[2 * p + 1][0], bf[2 * p + 1][1],
                        bAddr[p] + bStg + kOff);
#pragma unroll
            for (int mi = 0; mi < 4; ++mi)
#pragma unroll
                for (int ni = 0; ni < 8; ++ni) {
                    asm volatile(
                        "mma.sync.aligned.m16n8k8.row.col.f32.tf32.tf32.f32 "
                        "{%0,%1,%2,%3}, {%4,%5,%6,%7}, {%8,%9}, {%0,%1,%2,%3};\n"
                        : "+f"(acc[mi][ni][0]), "+f"(acc[mi][ni][1]),
                          "+f"(acc[mi][ni][2]), "+f"(acc[mi][ni][3])
                        : "r"(af[mi][0]), "r"(af[mi][1]), "r"(af[mi][2]), "r"(af[mi][3]),
                          "r"(bf[ni][0]), "r"(bf[ni][1]));
                }
        }
    }

    // epilogue: C = acc + bias
#pragma unroll
    for (int mi = 0; mi < 4; ++mi) {
        int r0 = bM + wm * 64 + mi * 16 + (lane >> 2);
#pragma unroll
        for (int ni = 0; ni < 8; ++ni) {
            int c = bN + wn * 64 + ni * 8 + (lane & 3) * 2;
            float b0 = bias[c], b1v = bias[c + 1];
            float2 v0 = make_float2(acc[mi][ni][0] + b0, acc[mi][ni][1] + b1v);
            float2 v1 = make_float2(acc[mi][ni][2] + b0, acc[mi][ni][3] + b1v);
            *reinterpret_cast<float2*>(&C[(size_t)r0 * N + c])       = v0;
            *reinterpret_cast<float2*>(&C[(size_t)(r0 + 8) * N + c]) = v1;
        }
    }
}

// ------------------------------------------------------------------
// launch
// ------------------------------------------------------------------
extern "C" void kernel_launch(void* const* d_in, const int* in_sizes, int n_in,
                              void* d_out, int out_size) {
    const float* x     = (const float*)d_in[0];
    const float* w1    = (const float*)d_in[1];
    const float* b1    = (const float*)d_in[2];
    const float* c1    = (const float*)d_in[3];
    const float* s1    = (const float*)d_in[4];
    const float* gamma = (const float*)d_in[5];
    const float* beta  = (const float*)d_in[6];
    const float* w2    = (const float*)d_in[7];
    const float* b2    = (const float*)d_in[8];
    const float* c2    = (const float*)d_in[9];
    const float* s2    = (const float*)d_in[10];
    float* out = (float*)d_out;

    cudaFuncSetAttribute(gemm_tf32_kernel,
                         cudaFuncAttributeMaxDynamicSharedMemorySize, GEMM_SMEM);

    void *pA, *pW1, *pW2, *pH1, *pB1, *pB2, *pC1d0, *pC2d0;
    cudaGetSymbolAddress(&pA,    g_Aexp);
    cudaGetSymbolAddress(&pW1,   g_W1f);
    cudaGetSymbolAddress(&pW2,   g_W2f);
    cudaGetSymbolAddress(&pH1,   g_H1);
    cudaGetSymbolAddress(&pB1,   g_bias1);
    cudaGetSymbolAddress(&pB2,   g_bias2);
    cudaGetSymbolAddress(&pC1d0, g_c1d0);
    cudaGetSymbolAddress(&pC2d0, g_c2d0);

    // weight fusion + bias (staged, coalesced reductions)
    fuse_w1_kernel<<<(H_DIM * IN_DIM + 255) / 256, 256>>>(w1, c1, s1);
    fuse_w2_kernel<<<(OUT_DIM * H_DIM + 255) / 256, 256>>>(w2, c2, s2);
    bias_reduce_kernel<<<H_DIM, 256>>>((const float*)pC1d0, b1, (float*)pB1, IN_DIM);
    bias_reduce_kernel<<<OUT_DIM, 256>>>((const float*)pC2d0, b2, (float*)pB2, H_DIM);

    // layer 1
    expand_x_kernel<<<(B_DIM * IN_DIM) / 256, 256>>>(x);
    {
        dim3 grid(H_DIM / GBN, B_DIM / GBM);   // (8, 64)
        gemm_tf32_kernel<<<grid, 256, GEMM_SMEM>>>(
            (const float*)pA, (const float*)pW1, (const float*)pB1,
            (float*)pH1, B_DIM, H_DIM, K_TOT);
    }

    // batchnorm stats
    bn_part_kernel<<<dim3(H_DIM / 256, 32), 256>>>();
    bn_fin_kernel<<<H_DIM / 256, 256>>>(gamma, beta);

    // layer 2
    expand_h_kernel<<<(B_DIM * H_DIM) / 256, 256>>>();
    {
        dim3 grid(OUT_DIM / GBN, B_DIM / GBM); // (2, 64)
        gemm_tf32_kernel<<<grid, 256, GEMM_SMEM>>>(
            (const float*)pA, (const float*)pW2, (const float*)pB2,
            out, B_DIM, OUT_DIM, K_TOT);
    }
}

// round 5
// speedup vs baseline: 2.0438x; 1.8535x over previous
#include <cuda_runtime.h>
#include <cuda_fp16.h>
#include <cstdint>
#include <cstdio>

// ------------------------------------------------------------------
// Problem constants
// ------------------------------------------------------------------
#define B_DIM   8192
#define IN_DIM  2048
#define H_DIM   2048
#define OUT_DIM 512
#define DEGP1   5
#define K_TOT (IN_DIM * DEGP1)   // 10240
#define BN_EPS 1e-5f
#define WSCALE 256.0f            // weight pre-scale (keeps fp16 normals)
#define INV_WSCALE (1.0f / 256.0f)

// ------------------------------------------------------------------
// Scratch (device globals; no runtime allocation)
// ------------------------------------------------------------------
__device__ __half g_Aexp[(size_t)B_DIM * K_TOT];    // expanded activations (fp16)
__device__ __half g_W1f [(size_t)H_DIM * K_TOT];    // fused W1 [H][K] (fp16, x256)
__device__ __half g_W2f [(size_t)OUT_DIM * K_TOT];  // fused W2 [OUT][K] (fp16, x256)
__device__ float  g_H1  [(size_t)B_DIM * H_DIM];    // layer-1 pre-BN output
__device__ float  g_c1d0[(size_t)H_DIM * IN_DIM];   // s1[h]*c1[i,h,0] staged coalesced
__device__ float  g_c2d0[(size_t)OUT_DIM * H_DIM];
__device__ float  g_bias1[H_DIM];
__device__ float  g_bias2[OUT_DIM];
__device__ float  g_partS [32 * H_DIM];
__device__ float  g_partS2[32 * H_DIM];
__device__ float  g_bnScale[H_DIM];
__device__ float  g_bnShift[H_DIM];

// ------------------------------------------------------------------
// helpers
// ------------------------------------------------------------------
__device__ __forceinline__ void ldsm_x4(uint32_t& r0, uint32_t& r1,
                                        uint32_t& r2, uint32_t& r3, uint32_t addr) {
    asm volatile("ldmatrix.sync.aligned.m8n8.x4.shared.b16 {%0,%1,%2,%3}, [%4];"
                 : "=r"(r0), "=r"(r1), "=r"(r2), "=r"(r3) : "r"(addr));
}

// ------------------------------------------------------------------
// Weight fusion (+ staged d=0 slice for fast bias reduction)
// ------------------------------------------------------------------
__global__ void fuse_w1_kernel(const float* __restrict__ w1,
                               const float* __restrict__ c1,
                               const float* __restrict__ s1) {
    long idx = (long)blockIdx.x * blockDim.x + threadIdx.x;
    if (idx >= (long)H_DIM * IN_DIM) return;
    int h = (int)(idx / IN_DIM);
    int i = (int)(idx % IN_DIM);
    float s = s1[h];
    __half* dst = g_W1f + (size_t)h * K_TOT;
    dst[i] = __float2half_rn(WSCALE * w1[(size_t)h * IN_DIM + i]);
    const float* cp = c1 + ((size_t)i * H_DIM + h) * DEGP1;
    g_c1d0[idx] = s * cp[0];
#pragma unroll
    for (int d = 1; d < DEGP1; ++d)
        dst[(size_t)d * IN_DIM + i] = __float2half_rn(WSCALE * s * cp[d]);
}

__global__ void fuse_w2_kernel(const float* __restrict__ w2,
                               const float* __restrict__ c2,
                               const float* __restrict__ s2) {
    long idx = (long)blockIdx.x * blockDim.x + threadIdx.x;
    if (idx >= (long)OUT_DIM * H_DIM) return;
    int o  = (int)(idx / H_DIM);
    int hh = (int)(idx % H_DIM);
    float s = s2[o];
    __half* dst = g_W2f + (size_t)o * K_TOT;
    dst[hh] = __float2half_rn(WSCALE * w2[(size_t)o * H_DIM + hh]);
    const float* cp = c2 + ((size_t)hh * OUT_DIM + o) * DEGP1;
    g_c2d0[idx] = s * cp[0];
#pragma unroll
    for (int d = 1; d < DEGP1; ++d)
        dst[(size_t)d * H_DIM + hh] = __float2half_rn(WSCALE * s * cp[d]);
}

// bias[o] = b[o] + sum_j staged[o*len + j]   (contiguous, one block per o)
__global__ void bias_reduce_kernel(const float* __restrict__ staged,
                                   const float* __restrict__ b,
                                   float* __restrict__ dst, int len) {
    __shared__ float red[256];
    int o = blockIdx.x;
    const float* src = staged + (size_t)o * len;
    float s = 0.f;
    for (int j = threadIdx.x; j < len; j += 256) s += src[j];
    red[threadIdx.x] = s;
    __syncthreads();
    for (int st = 128; st > 0; st >>= 1) {
        if (threadIdx.x < st) red[threadIdx.x] += red[threadIdx.x + st];
        __syncthreads();
    }
    if (threadIdx.x == 0) dst[o] = b[o] + red[0];
}

// ------------------------------------------------------------------
// Chebyshev expansion (fp16 outputs)
// ------------------------------------------------------------------
__global__ void expand_x_kernel(const float* __restrict__ X) {
    long idx = (long)blockIdx.x * blockDim.x + threadIdx.x;
    if (idx >= (long)B_DIM * IN_DIM) return;
    int r = (int)(idx / IN_DIM);
    int c = (int)(idx % IN_DIM);
    float x = X[idx];
    float t  = tanhf(x);
    float T2 = 2.f * t * t - 1.f;
    float T3 = 2.f * t * T2 - t;
    float T4 = 2.f * t * T3 - T2;
    __half* dst = g_Aexp + (size_t)r * K_TOT;
    dst[c]              = __float2half_rn(x);
    dst[IN_DIM + c]     = __float2half_rn(t);
    dst[2 * IN_DIM + c] = __float2half_rn(T2);
    dst[3 * IN_DIM + c] = __float2half_rn(T3);
    dst[4 * IN_DIM + c] = __float2half_rn(T4);
}

__global__ void expand_h_kernel() {
    long idx = (long)blockIdx.x * blockDim.x + threadIdx.x;
    if (idx >= (long)B_DIM * H_DIM) return;
    int r = (int)(idx / H_DIM);
    int c = (int)(idx % H_DIM);
    float y = g_bnScale[c] * g_H1[idx] + g_bnShift[c];
    float t  = tanhf(y);
    float T2 = 2.f * t * t - 1.f;
    float T3 = 2.f * t * T2 - t;
    float T4 = 2.f * t * T3 - T2;
    __half* dst = g_Aexp + (size_t)r * K_TOT;
    dst[c]             = __float2half_rn(y);
    dst[H_DIM + c]     = __float2half_rn(t);
    dst[2 * H_DIM + c] = __float2half_rn(T2);
    dst[3 * H_DIM + c] = __float2half_rn(T3);
    dst[4 * H_DIM + c] = __float2half_rn(T4);
}

// ------------------------------------------------------------------
// BatchNorm statistics (deterministic 2-stage)
// ------------------------------------------------------------------
__global__ void bn_part_kernel() {   // grid (H/256, 32), block 256
    int col = blockIdx.x * 256 + threadIdx.x;
    int r0  = blockIdx.y * 256;
    float s = 0.f, s2 = 0.f;
    for (int r = 0; r < 256; ++r) {
        float v = g_H1[(size_t)(r0 + r) * H_DIM + col];
        s  += v;
        s2 += v * v;
    }
    g_partS [blockIdx.y * H_DIM + col] = s;
    g_partS2[blockIdx.y * H_DIM + col] = s2;
}

__global__ void bn_fin_kernel(const float* __restrict__ gamma,
                              const float* __restrict__ beta) {
    int col = blockIdx.x * blockDim.x + threadIdx.x;
    if (col >= H_DIM) return;
    float s = 0.f, s2 = 0.f;
    for (int p = 0; p < 32; ++p) {
        s  += g_partS [p * H_DIM + col];
        s2 += g_partS2[p * H_DIM + col];
    }
    float invB = 1.f / (float)B_DIM;
    float mu  = s * invB;
    float var = s2 * invB - mu * mu;
    float inv = rsqrtf(var + BN_EPS);
    float sc  = gamma[col] * inv;
    g_bnScale[col] = sc;
    g_bnShift[col] = beta[col] - mu * sc;
}

// ------------------------------------------------------------------
// fp16 tensor-core GEMM: C = (A[M,K] * B[N,K]^T) * invScale + bias
// 128x256 block tile, 64x64 warp tile, 8 warps, GBK=64, 4-stage cp.async,
// ldmatrix.x4 feeding, mma.m16n8k16.f16 with fp32 accumulate.
// ------------------------------------------------------------------
#define GBM 128
#define GBN 256
#define GBK 64                                    // halves per K chunk
#define GSTAGES 4
#define LDP 72                                    // GBK + 8 pad (144B row stride: LDSM conflict-free)
#define A_STG (GBM * LDP)                         // halves per A stage
#define B_STG (GBN * LDP)
#define GEMM_SMEM (GSTAGES * (A_STG + B_STG) * 2) // 221184 B

__global__ void __launch_bounds__(256, 1)
gemm_fp16_kernel(const __half* __restrict__ A, const __half* __restrict__ B,
                 const float* __restrict__ bias, float* __restrict__ C,
                 int M, int N, int K) {
    extern __shared__ __half smem[];
    __half* As = smem;                       // [GSTAGES][GBM][LDP]
    __half* Bs = smem + GSTAGES * A_STG;     // [GSTAGES][GBN][LDP]

    const int tid  = threadIdx.x;
    const int lane = tid & 31;
    const int warp = tid >> 5;
    const int wm = warp >> 2;     // 0..1  -> 64-row warp tile
    const int wn = warp & 3;      // 0..3  -> 64-col warp tile

    const int bM = blockIdx.y * GBM;
    const int bN = blockIdx.x * GBN;

    const __half* Ag = A + (size_t)bM * K;
    const __half* Bg = B + (size_t)bN * K;

    const int ldr = tid >> 3;           // 0..31 (row within 32-row group)
    const int ldc = (tid & 7) * 8;      // 8 halves = 16B

    uint32_t asBase = (uint32_t)__cvta_generic_to_shared(As);
    uint32_t bsBase = (uint32_t)__cvta_generic_to_shared(Bs);

    auto loadTile = [&](int stage, int kt) {
        const __half* ga = Ag + (size_t)ldr * K + kt * GBK + ldc;
        const __half* gb = Bg + (size_t)ldr * K + kt * GBK + ldc;
        uint32_t sa  = asBase + (uint32_t)(((stage * GBM + ldr) * LDP + ldc) * 2);
        uint32_t sbp = bsBase + (uint32_t)(((stage * GBN + ldr) * LDP + ldc) * 2);
#pragma unroll
        for (int i = 0; i < 4; ++i)
            asm volatile("cp.async.cg.shared.global [%0], [%1], 16;\n"
                         :: "r"(sa + i * 32 * LDP * 2), "l"(ga + (size_t)i * 32 * K));
#pragma unroll
        for (int i = 0; i < 8; ++i)
            asm volatile("cp.async.cg.shared.global [%0], [%1], 16;\n"
                         :: "r"(sbp + i * 32 * LDP * 2), "l"(gb + (size_t)i * 32 * K));
    };

    float acc[4][8][4];
#pragma unroll
    for (int mi = 0; mi < 4; ++mi)
#pragma unroll
        for (int ni = 0; ni < 8; ++ni)
#pragma unroll
            for (int r = 0; r < 4; ++r) acc[mi][ni][r] = 0.f;

    const int KT = K / GBK;   // 160
#pragma unroll
    for (int s = 0; s < GSTAGES - 1; ++s) {
        loadTile(s, s);
        asm volatile("cp.async.commit_group;\n");
    }

    // -------- ldmatrix per-lane base addresses --------
    // x4 tile id j = lane>>3, row within tile = lane&7.
    const int jj = lane >> 3;
    const int lr = lane & 7;
    // A (m16n8k16): tiles {r0-7/k0-7, r8-15/k0-7, r0-7/k8-15, r8-15/k8-15}
    uint32_t aAddr[4];
#pragma unroll
    for (int mi = 0; mi < 4; ++mi) {
        int row = wm * 64 + mi * 16 + ((jj & 1) << 3) + lr;
        aAddr[mi] = asBase + (uint32_t)((row * LDP) * 2 + ((jj >> 1) << 4));
    }
    // B: pair p covers ni=2p,2p+1: tiles {n0-7/k0-7, n0-7/k8-15, n8-15/k0-7, n8-15/k8-15}
    uint32_t bAddr[4];
#pragma unroll
    for (int p = 0; p < 4; ++p) {
        int row = wn * 64 + p * 16 + ((jj >> 1) << 3) + lr;
        bAddr[p] = bsBase + (uint32_t)((row * LDP) * 2 + ((jj & 1) << 4));
    }

    for (int kt = 0; kt < KT; ++kt) {
        asm volatile("cp.async.wait_group %0;\n" :: "n"(GSTAGES - 2));
        __syncthreads();
        int s = kt % GSTAGES;
        int nkt = kt + GSTAGES - 1;
        if (nkt < KT) loadTile(nkt % GSTAGES, nkt);
        asm volatile("cp.async.commit_group;\n");

        const uint32_t aStg = (uint32_t)(s * A_STG * 2);
        const uint32_t bStg = (uint32_t)(s * B_STG * 2);
#pragma unroll
        for (int kk = 0; kk < GBK / 16; ++kk) {     // 4 k16 steps
            const uint32_t kOff = kk * 32;          // 16 halves = 32 bytes
            uint32_t af[4][4], bf[8][2];
#pragma unroll
            for (int mi = 0; mi < 4; ++mi)
                ldsm_x4(af[mi][0], af[mi][1], af[mi][2], af[mi][3],
                        aAddr[mi] + aStg + kOff);
#pragma unroll
            for (int p = 0; p < 4; ++p)
                ldsm_x4(bf[2 * p][0], bf[2 * p][1], bf[2 * p + 1][0], bf[2 * p + 1][1],
                        bAddr[p] + bStg + kOff);
#pragma unroll
            for (int mi = 0; mi < 4; ++mi)
#pragma unroll
                for (int ni = 0; ni < 8; ++ni) {
                    asm volatile(
                        "mma.sync.aligned.m16n8k16.row.col.f32.f16.f16.f32 "
                        "{%0,%1,%2,%3}, {%4,%5,%6,%7}, {%8,%9}, {%0,%1,%2,%3};\n"
                        : "+f"(acc[mi][ni][0]), "+f"(acc[mi][ni][1]),
                          "+f"(acc[mi][ni][2]), "+f"(acc[mi][ni][3])
                        : "r"(af[mi][0]), "r"(af[mi][1]), "r"(af[mi][2]), "r"(af[mi][3]),
                          "r"(bf[ni][0]), "r"(bf[ni][1]));
                }
        }
    }

    // epilogue: C = acc * invScale + bias
#pragma unroll
    for (int mi = 0; mi < 4; ++mi) {
        int r0 = bM + wm * 64 + mi * 16 + (lane >> 2);
#pragma unroll
        for (int ni = 0; ni < 8; ++ni) {
            int c = bN + wn * 64 + ni * 8 + (lane & 3) * 2;
            float b0 = bias[c], b1v = bias[c + 1];
            float2 v0 = make_float2(fmaf(acc[mi][ni][0], INV_WSCALE, b0),
                                    fmaf(acc[mi][ni][1], INV_WSCALE, b1v));
            float2 v1 = make_float2(fmaf(acc[mi][ni][2], INV_WSCALE, b0),
                                    fmaf(acc[mi][ni][3], INV_WSCALE, b1v));
            *reinterpret_cast<float2*>(&C[(size_t)r0 * N + c])       = v0;
            *reinterpret_cast<float2*>(&C[(size_t)(r0 + 8) * N + c]) = v1;
        }
    }
}

// ------------------------------------------------------------------
// launch
// ------------------------------------------------------------------
extern "C" void kernel_launch(void* const* d_in, const int* in_sizes, int n_in,
                              void* d_out, int out_size) {
    const float* x     = (const float*)d_in[0];
    const float* w1    = (const float*)d_in[1];
    const float* b1    = (const float*)d_in[2];
    const float* c1    = (const float*)d_in[3];
    const float* s1    = (const float*)d_in[4];
    const float* gamma = (const float*)d_in[5];
    const float* beta  = (const float*)d_in[6];
    const float* w2    = (const float*)d_in[7];
    const float* b2    = (const float*)d_in[8];
    const float* c2    = (const float*)d_in[9];
    const float* s2    = (const float*)d_in[10];
    float* out = (float*)d_out;

    cudaFuncSetAttribute(gemm_fp16_kernel,
                         cudaFuncAttributeMaxDynamicSharedMemorySize, GEMM_SMEM);

    void *pA, *pW1, *pW2, *pH1, *pB1, *pB2, *pC1d0, *pC2d0;
    cudaGetSymbolAddress(&pA,    g_Aexp);
    cudaGetSymbolAddress(&pW1,   g_W1f);
    cudaGetSymbolAddress(&pW2,   g_W2f);
    cudaGetSymbolAddress(&pH1,   g_H1);
    cudaGetSymbolAddress(&pB1,   g_bias1);
    cudaGetSymbolAddress(&pB2,   g_bias2);
    cudaGetSymbolAddress(&pC1d0, g_c1d0);
    cudaGetSymbolAddress(&pC2d0, g_c2d0);

    // weight fusion + bias (staged, coalesced reductions)
    fuse_w1_kernel<<<(H_DIM * IN_DIM + 255) / 256, 256>>>(w1, c1, s1);
    fuse_w2_kernel<<<(OUT_DIM * H_DIM + 255) / 256, 256>>>(w2, c2, s2);
    bias_reduce_kernel<<<H_DIM, 256>>>((const float*)pC1d0, b1, (float*)pB1, IN_DIM);
    bias_reduce_kernel<<<OUT_DIM, 256>>>((const float*)pC2d0, b2, (float*)pB2, H_DIM);

    // layer 1
    expand_x_kernel<<<(B_DIM * IN_DIM) / 256, 256>>>(x);
    {
        dim3 grid(H_DIM / GBN, B_DIM / GBM);   // (8, 64)
        gemm_fp16_kernel<<<grid, 256, GEMM_SMEM>>>(
            (const __half*)pA, (const __half*)pW1, (const float*)pB1,
            (float*)pH1, B_DIM, H_DIM, K_TOT);
    }

    // batchnorm stats
    bn_part_kernel<<<dim3(H_DIM / 256, 32), 256>>>();
    bn_fin_kernel<<<H_DIM / 256, 256>>>(gamma, beta);

    // layer 2
    expand_h_kernel<<<(B_DIM * H_DIM) / 256, 256>>>();
    {
        dim3 grid(OUT_DIM / GBN, B_DIM / GBM); // (2, 64)
        gemm_fp16_kernel<<<grid, 256, GEMM_SMEM>>>(
            (const __half*)pA, (const __half*)pW2, (const float*)pB2,
            out, B_DIM, OUT_DIM, K_TOT);
    }
}

// round 6
// speedup vs baseline: 2.0571x; 1.0065x over previous
#include <cuda_runtime.h>
#include <cuda_fp16.h>
#include <cstdint>
#include <cstdio>

// ------------------------------------------------------------------
// Problem constants
// ------------------------------------------------------------------
#define B_DIM   8192
#define IN_DIM  2048
#define H_DIM   2048
#define OUT_DIM 512
#define DEGP1   5
#define K_TOT (IN_DIM * DEGP1)   // 10240 (both layers)
#define BN_EPS 1e-5f
#define WSCALE 256.0f
#define INV_WSCALE (1.0f / 256.0f)

// ------------------------------------------------------------------
// Scratch (device globals; no runtime allocation)
// ------------------------------------------------------------------
__device__ __half g_Aexp[(size_t)B_DIM * K_TOT];    // expanded activations (fp16)
__device__ __half g_W1f [(size_t)H_DIM * K_TOT];    // fused W1 (fp16, x256)
__device__ __half g_W2f [(size_t)OUT_DIM * K_TOT];  // fused W2 (fp16, x256)
__device__ __half g_H1h [(size_t)B_DIM * H_DIM];    // layer-1 pre-BN output (fp16)
__device__ float  g_c1d0[(size_t)H_DIM * IN_DIM];   // s1[h]*c1[i,h,0], transposed
__device__ float  g_c2d0[(size_t)OUT_DIM * H_DIM];
__device__ float  g_bias1[H_DIM];
__device__ float  g_bias2[OUT_DIM];
__device__ float  g_partS [32 * H_DIM];
__device__ float  g_partS2[32 * H_DIM];
__device__ float  g_bnScale[H_DIM];
__device__ float  g_bnShift[H_DIM];

// ------------------------------------------------------------------
// helpers
// ------------------------------------------------------------------
__device__ __forceinline__ void ldsm_x4(uint32_t& r0, uint32_t& r1,
                                        uint32_t& r2, uint32_t& r3, uint32_t addr) {
    asm volatile("ldmatrix.sync.aligned.m8n8.x4.shared.b16 {%0,%1,%2,%3}, [%4];"
                 : "=r"(r0), "=r"(r1), "=r"(r2), "=r"(r3) : "r"(addr));
}

// ------------------------------------------------------------------
// Coefficient fusion via smem transpose.
// c[i][h][d] (i in [0,In), h in [0,Hh), d in [0,5)) ->
//   Wf[h][d*In + i] = half(WSCALE * s[h] * c[i][h][d])   (d = 1..4)
//   cd0[h*In + i]   = s[h] * c[i][h][0]
// Reads coalesced along (h,d); writes coalesced along i.
// grid (In/32, Hh/32), block 256.
// ------------------------------------------------------------------
__global__ void fuse_c_kernel(const float* __restrict__ c,
                              const float* __restrict__ s,
                              __half* __restrict__ Wf,
                              float* __restrict__ cd0,
                              int In, int Hh) {
    __shared__ float sm[160][33];
    const int tid = threadIdx.x;
    const int i0 = blockIdx.x * 32;
    const int h0 = blockIdx.y * 32;

    // read: 32 i x 160 (h,d) elements
    for (int e = tid; e < 32 * 160; e += 256) {
        int ii  = e / 160;
        int pos = e % 160;
        sm[pos][ii] = c[(size_t)(i0 + ii) * Hh * DEGP1 + (size_t)h0 * DEGP1 + pos];
    }
    __syncthreads();

    const int lane = tid & 31;   // i index
    for (int hl = tid >> 5; hl < 32; hl += 8) {
        float sv = s[h0 + hl];
        cd0[(size_t)(h0 + hl) * In + i0 + lane] = sv * sm[hl * DEGP1][lane];
        __half* wrow = Wf + (size_t)(h0 + hl) * (In * DEGP1);
#pragma unroll
        for (int d = 1; d < DEGP1; ++d)
            wrow[d * In + i0 + lane] =
                __float2half_rn(WSCALE * sv * sm[hl * DEGP1 + d][lane]);
    }
}

// W base block (d=0): Wf[row][col] = half(WSCALE * w[row][col])
__global__ void base_w_kernel(const float* __restrict__ w,
                              __half* __restrict__ Wf, int In, long total) {
    long idx = (long)blockIdx.x * blockDim.x + threadIdx.x;
    if (idx >= total) return;
    int row = (int)(idx / In);
    int col = (int)(idx % In);
    Wf[(size_t)row * (In * DEGP1) + col] = __float2half_rn(WSCALE * w[idx]);
}

// bias[o] = b[o] + sum_j staged[o*len + j]
__global__ void bias_reduce_kernel(const float* __restrict__ staged,
                                   const float* __restrict__ b,
                                   float* __restrict__ dst, int len) {
    __shared__ float red[256];
    int o = blockIdx.x;
    const float* src = staged + (size_t)o * len;
    float s = 0.f;
    for (int j = threadIdx.x; j < len; j += 256) s += src[j];
    red[threadIdx.x] = s;
    __syncthreads();
    for (int st = 128; st > 0; st >>= 1) {
        if (threadIdx.x < st) red[threadIdx.x] += red[threadIdx.x + st];
        __syncthreads();
    }
    if (threadIdx.x == 0) dst[o] = b[o] + red[0];
}

// ------------------------------------------------------------------
// Chebyshev expansion (vectorized: 2 columns / thread)
// ------------------------------------------------------------------
__global__ void expand_x_kernel(const float* __restrict__ X) {
    long idx = (long)blockIdx.x * blockDim.x + threadIdx.x;   // over B*IN/2
    if (idx >= (long)B_DIM * IN_DIM / 2) return;
    int r  = (int)(idx / (IN_DIM / 2));
    int cp = (int)(idx % (IN_DIM / 2));
    float2 xv = reinterpret_cast<const float2*>(X)[idx];

    float t0 = tanhf(xv.x), t1 = tanhf(xv.y);
    float a2 = 2.f * t0 * t0 - 1.f,  b2 = 2.f * t1 * t1 - 1.f;
    float a3 = 2.f * t0 * a2 - t0,   b3 = 2.f * t1 * b2 - t1;
    float a4 = 2.f * t0 * a3 - a2,   b4 = 2.f * t1 * b3 - b2;

    __half* dst = g_Aexp + (size_t)r * K_TOT;
    reinterpret_cast<__half2*>(dst)[cp]                      = __floats2half2_rn(xv.x, xv.y);
    reinterpret_cast<__half2*>(dst + IN_DIM)[cp]             = __floats2half2_rn(t0, t1);
    reinterpret_cast<__half2*>(dst + 2 * IN_DIM)[cp]         = __floats2half2_rn(a2, b2);
    reinterpret_cast<__half2*>(dst + 3 * IN_DIM)[cp]         = __floats2half2_rn(a3, b3);
    reinterpret_cast<__half2*>(dst + 4 * IN_DIM)[cp]         = __floats2half2_rn(a4, b4);
}

__global__ void expand_h_kernel() {
    long idx = (long)blockIdx.x * blockDim.x + threadIdx.x;   // over B*H/2
    if (idx >= (long)B_DIM * H_DIM / 2) return;
    int r  = (int)(idx / (H_DIM / 2));
    int cp = (int)(idx % (H_DIM / 2));
    int c  = cp * 2;
    __half2 hv = reinterpret_cast<const __half2*>(g_H1h)[idx];
    float2 sc = reinterpret_cast<const float2*>(g_bnScale)[cp];
    float2 sh = reinterpret_cast<const float2*>(g_bnShift)[cp];
    (void)c;
    float y0 = fmaf(sc.x, __half2float(hv.x), sh.x);
    float y1 = fmaf(sc.y, __half2float(hv.y), sh.y);

    float t0 = tanhf(y0), t1 = tanhf(y1);
    float a2 = 2.f * t0 * t0 - 1.f,  b2 = 2.f * t1 * t1 - 1.f;
    float a3 = 2.f * t0 * a2 - t0,   b3 = 2.f * t1 * b2 - t1;
    float a4 = 2.f * t0 * a3 - a2,   b4 = 2.f * t1 * b3 - b2;

    __half* dst = g_Aexp + (size_t)r * K_TOT;
    reinterpret_cast<__half2*>(dst)[cp]                      = __floats2half2_rn(y0, y1);
    reinterpret_cast<__half2*>(dst + H_DIM)[cp]              = __floats2half2_rn(t0, t1);
    reinterpret_cast<__half2*>(dst + 2 * H_DIM)[cp]          = __floats2half2_rn(a2, b2);
    reinterpret_cast<__half2*>(dst + 3 * H_DIM)[cp]          = __floats2half2_rn(a3, b3);
    reinterpret_cast<__half2*>(dst + 4 * H_DIM)[cp]          = __floats2half2_rn(a4, b4);
}

// ------------------------------------------------------------------
// BatchNorm statistics (deterministic 2-stage, half2 reads)
// ------------------------------------------------------------------
__global__ void bn_part_kernel() {   // grid (H/512, 32), block 256; 2 cols/thread
    int cp = blockIdx.x * 256 + threadIdx.x;    // column pair
    int r0 = blockIdx.y * 256;
    float s0 = 0.f, s1 = 0.f, q0 = 0.f, q1 = 0.f;
    for (int r = 0; r < 256; ++r) {
        __half2 v = reinterpret_cast<const __half2*>(
            g_H1h + (size_t)(r0 + r) * H_DIM)[cp];
        float v0 = __half2float(v.x), v1 = __half2float(v.y);
        s0 += v0; s1 += v1;
        q0 += v0 * v0; q1 += v1 * v1;
    }
    reinterpret_cast<float2*>(g_partS  + blockIdx.y * H_DIM)[cp] = make_float2(s0, s1);
    reinterpret_cast<float2*>(g_partS2 + blockIdx.y * H_DIM)[cp] = make_float2(q0, q1);
}

__global__ void bn_fin_kernel(const float* __restrict__ gamma,
                              const float* __restrict__ beta) {
    int col = blockIdx.x * blockDim.x + threadIdx.x;
    if (col >= H_DIM) return;
    float s = 0.f, s2 = 0.f;
    for (int p = 0; p < 32; ++p) {
        s  += g_partS [p * H_DIM + col];
        s2 += g_partS2[p * H_DIM + col];
    }
    float invB = 1.f / (float)B_DIM;
    float mu  = s * invB;
    float var = s2 * invB - mu * mu;
    float inv = rsqrtf(var + BN_EPS);
    float sc  = gamma[col] * inv;
    g_bnScale[col] = sc;
    g_bnShift[col] = beta[col] - mu * sc;
}

// ------------------------------------------------------------------
// fp16 tensor-core GEMM: C = (A[M,K] * B[N,K]^T) * invScale + bias
// 128 x GBNT block tile, 8 warps (warp tile 64 x GBNT/4), GBK=64,
// 4-stage cp.async, ldmatrix.x4 feeding, mma.m16n8k16 fp32 accum.
// Templated on GBNT (256 or 128) and output type (half or float).
// ------------------------------------------------------------------
#define GBM 128
#define GBK 64
#define GSTAGES 4
#define LDP 72                                     // GBK + 8 pad
#define A_STG (GBM * LDP)

template <int GBNT, typename OutT>
__global__ void __launch_bounds__(256, 1)
gemm_fp16_kernel(const __half* __restrict__ A, const __half* __restrict__ B,
                 const float* __restrict__ bias, OutT* __restrict__ C,
                 int M, int N, int K) {
    constexpr int NI   = GBNT / 32;    // n-tiles (8-wide) per warp
    constexpr int WN   = GBNT / 4;     // warp n extent
    constexpr int BSTG = GBNT * LDP;

    extern __shared__ __half smem[];
    __half* As = smem;                       // [GSTAGES][GBM][LDP]
    __half* Bs = smem + GSTAGES * A_STG;     // [GSTAGES][GBNT][LDP]

    const int tid  = threadIdx.x;
    const int lane = tid & 31;
    const int warp = tid >> 5;
    const int wm = warp >> 2;     // 0..1
    const int wn = warp & 3;      // 0..3

    const int bM = blockIdx.y * GBM;
    const int bN = blockIdx.x * GBNT;

    const __half* Ag = A + (size_t)bM * K;
    const __half* Bg = B + (size_t)bN * K;

    const int ldr = tid >> 3;           // 0..31
    const int ldc = (tid & 7) * 8;      // 8 halves = 16B

    uint32_t asBase = (uint32_t)__cvta_generic_to_shared(As);
    uint32_t bsBase = (uint32_t)__cvta_generic_to_shared(Bs);

    auto loadTile = [&](int stage, int kt) {
        const __half* ga = Ag + (size_t)ldr * K + kt * GBK + ldc;
        const __half* gb = Bg + (size_t)ldr * K + kt * GBK + ldc;
        uint32_t sa  = asBase + (uint32_t)(((stage * GBM + ldr) * LDP + ldc) * 2);
        uint32_t sbp = bsBase + (uint32_t)(((stage * GBNT + ldr) * LDP + ldc) * 2);
#pragma unroll
        for (int i = 0; i < GBM / 32; ++i)
            asm volatile("cp.async.cg.shared.global [%0], [%1], 16;\n"
                         :: "r"(sa + i * 32 * LDP * 2), "l"(ga + (size_t)i * 32 * K));
#pragma unroll
        for (int i = 0; i < GBNT / 32; ++i)
            asm volatile("cp.async.cg.shared.global [%0], [%1], 16;\n"
                         :: "r"(sbp + i * 32 * LDP * 2), "l"(gb + (size_t)i * 32 * K));
    };

    float acc[4][NI][4];
#pragma unroll
    for (int mi = 0; mi < 4; ++mi)
#pragma unroll
        for (int ni = 0; ni < NI; ++ni)
#pragma unroll
            for (int r = 0; r < 4; ++r) acc[mi][ni][r] = 0.f;

    const int KT = K / GBK;
#pragma unroll
    for (int s = 0; s < GSTAGES - 1; ++s) {
        loadTile(s, s);
        asm volatile("cp.async.commit_group;\n");
    }

    const int jj = lane >> 3;
    const int lr = lane & 7;
    uint32_t aAddr[4];
#pragma unroll
    for (int mi = 0; mi < 4; ++mi) {
        int row = wm * 64 + mi * 16 + ((jj & 1) << 3) + lr;
        aAddr[mi] = asBase + (uint32_t)((row * LDP) * 2 + ((jj >> 1) << 4));
    }
    uint32_t bAddr[NI / 2];
#pragma unroll
    for (int p = 0; p < NI / 2; ++p) {
        int row = wn * WN + p * 16 + ((jj >> 1) << 3) + lr;
        bAddr[p] = bsBase + (uint32_t)((row * LDP) * 2 + ((jj & 1) << 4));
    }

    for (int kt = 0; kt < KT; ++kt) {
        asm volatile("cp.async.wait_group %0;\n" :: "n"(GSTAGES - 2));
        __syncthreads();
        int s = kt % GSTAGES;
        int nkt = kt + GSTAGES - 1;
        if (nkt < KT) loadTile(nkt % GSTAGES, nkt);
        asm volatile("cp.async.commit_group;\n");

        const uint32_t aStg = (uint32_t)(s * A_STG * 2);
        const uint32_t bStg = (uint32_t)(s * BSTG * 2);
#pragma unroll
        for (int kk = 0; kk < GBK / 16; ++kk) {
            const uint32_t kOff = kk * 32;
            uint32_t af[4][4], bf[NI][2];
#pragma unroll
            for (int mi = 0; mi < 4; ++mi)
                ldsm_x4(af[mi][0], af[mi][1], af[mi][2], af[mi][3],
                        aAddr[mi] + aStg + kOff);
#pragma unroll
            for (int p = 0; p < NI / 2; ++p)
                ldsm_x4(bf[2 * p][0], bf[2 * p][1], bf[2 * p + 1][0], bf[2 * p + 1][1],
                        bAddr[p] + bStg + kOff);
#pragma unroll
            for (int mi = 0; mi < 4; ++mi)
#pragma unroll
                for (int ni = 0; ni < NI; ++ni) {
                    asm volatile(
                        "mma.sync.aligned.m16n8k16.row.col.f32.f16.f16.f32 "
                        "{%0,%1,%2,%3}, {%4,%5,%6,%7}, {%8,%9}, {%0,%1,%2,%3};\n"
                        : "+f"(acc[mi][ni][0]), "+f"(acc[mi][ni][1]),
                          "+f"(acc[mi][ni][2]), "+f"(acc[mi][ni][3])
                        : "r"(af[mi][0]), "r"(af[mi][1]), "r"(af[mi][2]), "r"(af[mi][3]),
                          "r"(bf[ni][0]), "r"(bf[ni][1]));
                }
        }
    }

    // epilogue: C = acc * invScale + bias
#pragma unroll
    for (int mi = 0; mi < 4; ++mi) {
        int r0 = bM + wm * 64 + mi * 16 + (lane >> 2);
#pragma unroll
        for (int ni = 0; ni < NI; ++ni) {
            int c = bN + wn * WN + ni * 8 + (lane & 3) * 2;
            float b0 = bias[c], b1v = bias[c + 1];
            float f00 = fmaf(acc[mi][ni][0], INV_WSCALE, b0);
            float f01 = fmaf(acc[mi][ni][1], INV_WSCALE, b1v);
            float f10 = fmaf(acc[mi][ni][2], INV_WSCALE, b0);
            float f11 = fmaf(acc[mi][ni][3], INV_WSCALE, b1v);
            if constexpr (sizeof(OutT) == 2) {
                *reinterpret_cast<__half2*>(&C[(size_t)r0 * N + c]) =
                    __floats2half2_rn(f00, f01);
                *reinterpret_cast<__half2*>(&C[(size_t)(r0 + 8) * N + c]) =
                    __floats2half2_rn(f10, f11);
            } else {
                *reinterpret_cast<float2*>(&C[(size_t)r0 * N + c]) =
                    make_float2(f00, f01);
                *reinterpret_cast<float2*>(&C[(size_t)(r0 + 8) * N + c]) =
                    make_float2(f10, f11);
            }
        }
    }
}

#define SMEM1 (GSTAGES * (A_STG + 256 * LDP) * 2)   // 221184
#define SMEM2 (GSTAGES * (A_STG + 128 * LDP) * 2)   // 147456

// ------------------------------------------------------------------
// launch
// ------------------------------------------------------------------
extern "C" void kernel_launch(void* const* d_in, const int* in_sizes, int n_in,
                              void* d_out, int out_size) {
    const float* x     = (const float*)d_in[0];
    const float* w1    = (const float*)d_in[1];
    const float* b1    = (const float*)d_in[2];
    const float* c1    = (const float*)d_in[3];
    const float* s1    = (const float*)d_in[4];
    const float* gamma = (const float*)d_in[5];
    const float* beta  = (const float*)d_in[6];
    const float* w2    = (const float*)d_in[7];
    const float* b2    = (const float*)d_in[8];
    const float* c2    = (const float*)d_in[9];
    const float* s2    = (const float*)d_in[10];
    float* out = (float*)d_out;

    cudaFuncSetAttribute(gemm_fp16_kernel<256, __half>,
                         cudaFuncAttributeMaxDynamicSharedMemorySize, SMEM1);
    cudaFuncSetAttribute(gemm_fp16_kernel<128, float>,
                         cudaFuncAttributeMaxDynamicSharedMemorySize, SMEM2);

    void *pA, *pW1, *pW2, *pH1, *pB1, *pB2, *pC1d0, *pC2d0;
    cudaGetSymbolAddress(&pA,    g_Aexp);
    cudaGetSymbolAddress(&pW1,   g_W1f);
    cudaGetSymbolAddress(&pW2,   g_W2f);
    cudaGetSymbolAddress(&pH1,   g_H1h);
    cudaGetSymbolAddress(&pB1,   g_bias1);
    cudaGetSymbolAddress(&pB2,   g_bias2);
    cudaGetSymbolAddress(&pC1d0, g_c1d0);
    cudaGetSymbolAddress(&pC2d0, g_c2d0);

    // ---- weight fusion (transpose) + base blocks + biases ----
    {
        dim3 g1(IN_DIM / 32, H_DIM / 32);      // (64, 64)
        fuse_c_kernel<<<g1, 256>>>(c1, s1, (__half*)pW1, (float*)pC1d0, IN_DIM, H_DIM);
        dim3 g2(H_DIM / 32, OUT_DIM / 32);     // (64, 16)
        fuse_c_kernel<<<g2, 256>>>(c2, s2, (__half*)pW2, (float*)pC2d0, H_DIM, OUT_DIM);
    }
    base_w_kernel<<<((long)H_DIM * IN_DIM + 255) / 256, 256>>>(
        w1, (__half*)pW1, IN_DIM, (long)H_DIM * IN_DIM);
    base_w_kernel<<<((long)OUT_DIM * H_DIM + 255) / 256, 256>>>(
        w2, (__half*)pW2, H_DIM, (long)OUT_DIM * H_DIM);
    bias_reduce_kernel<<<H_DIM, 256>>>((const float*)pC1d0, b1, (float*)pB1, IN_DIM);
    bias_reduce_kernel<<<OUT_DIM, 256>>>((const float*)pC2d0, b2, (float*)pB2, H_DIM);

    // ---- layer 1 ----
    expand_x_kernel<<<(B_DIM * IN_DIM / 2 + 255) / 256, 256>>>(x);
    {
        dim3 grid(H_DIM / 256, B_DIM / GBM);   // (8, 64)
        gemm_fp16_kernel<256, __half><<<grid, 256, SMEM1>>>(
            (const __half*)pA, (const __half*)pW1, (const float*)pB1,
            (__half*)pH1, B_DIM, H_DIM, K_TOT);
    }

    // ---- batchnorm stats ----
    bn_part_kernel<<<dim3(H_DIM / 512, 32), 256>>>();
    bn_fin_kernel<<<H_DIM / 256, 256>>>(gamma, beta);

    // ---- layer 2 ----
    expand_h_kernel<<<(B_DIM * H_DIM / 2 + 255) / 256, 256>>>();
    {
        dim3 grid(OUT_DIM / 128, B_DIM / GBM); // (4, 64) = 256 CTAs
        gemm_fp16_kernel<128, float><<<grid, 256, SMEM2>>>(
            (const __half*)pA, (const __half*)pW2, (const float*)pB2,
            out, B_DIM, OUT_DIM, K_TOT);
    }
}